// round 1
// baseline (speedup 1.0000x reference)
#include <cuda_runtime.h>

#define NQ    12
#define DIM   4096
#define NL    4
#define NT    256
#define PAIRS (DIM/2)
#define KPT   (DIM/NT)     // 16 amplitudes per thread

struct cplx { float x, y; };

__device__ __forceinline__ cplx cmul(cplx a, cplx b) {
    return { a.x*b.x - a.y*b.y, a.x*b.y + a.y*b.x };
}
__device__ __forceinline__ cplx cadd(cplx a, cplx b) {
    return { a.x + b.x, a.y + b.y };
}
// C = A * B for 2x2 complex, layout {m00,m01,m10,m11}
__device__ __forceinline__ void mmul(const cplx* A, const cplx* B, cplx* C) {
    C[0] = cadd(cmul(A[0], B[0]), cmul(A[1], B[2]));
    C[1] = cadd(cmul(A[0], B[1]), cmul(A[1], B[3]));
    C[2] = cadd(cmul(A[2], B[0]), cmul(A[3], B[2]));
    C[3] = cadd(cmul(A[2], B[1]), cmul(A[3], B[3]));
}

__global__ __launch_bounds__(NT)
void qsim_kernel(const float* __restrict__ x,
                 const float* __restrict__ params,
                 float* __restrict__ out)
{
    __shared__ float2 st[DIM];            // 32 KB state
    __shared__ float2 U[NL][NQ][4];       // fused per-(layer,qubit) gates
    __shared__ float  red[NT / 32];

    const int t = threadIdx.x;
    const int b = blockIdx.x;

    // ---- init |0...0> ----
    for (int i = t; i < DIM; i += NT) st[i] = make_float2(0.f, 0.f);
    if (t == 0) st[0] = make_float2(1.f, 0.f);

    // ---- build 48 fused gate matrices (one thread each) ----
    if (t < NL * NQ) {
        const int l = t / NQ;
        const int q = t % NQ;
        const float xv = x[b];
        const float x1 = asinf(xv);
        const float x2 = acosf(xv * xv);

        float c, s;
        sincosf(0.5f * x1, &s, &c);
        cplx RY[4] = { {c,0.f}, {-s,0.f}, {s,0.f}, {c,0.f} };
        sincosf(0.5f * x2, &s, &c);
        cplx RZ[4] = { {c,-s}, {0.f,0.f}, {0.f,0.f}, {c,s} };

        const float t0 = params[q * (NL * 3) + l * 3 + 0];
        const float t1 = params[q * (NL * 3) + l * 3 + 1];
        const float t2 = params[q * (NL * 3) + l * 3 + 2];

        sincosf(0.5f * t0, &s, &c);
        cplx RX0[4] = { {c,0.f}, {0.f,-s}, {0.f,-s}, {c,0.f} };
        sincosf(0.5f * t1, &s, &c);
        cplx RZ1[4] = { {c,-s}, {0.f,0.f}, {0.f,0.f}, {c,s} };
        sincosf(0.5f * t2, &s, &c);
        cplx RX2[4] = { {c,0.f}, {0.f,-s}, {0.f,-s}, {c,0.f} };

        cplx A[4], B[4];
        mmul(RZ,  RY, A);   // RZ(x2) * RY(x1)
        mmul(RX0, A,  B);   // RX(t0) * ...
        mmul(RZ1, B,  A);   // RZ(t1) * ...
        mmul(RX2, A,  B);   // RX(t2) * ...   (applied last in time)
        #pragma unroll
        for (int m = 0; m < 4; m++) U[l][q][m] = make_float2(B[m].x, B[m].y);
    }

    // ---- precompute fused CNOT-chain permutation (gather indices) ----
    // new[i] = old[g0(g1(...g10(i)))], g_c flips bit(10-c) if bit(11-c) set
    int perm[KPT];
    #pragma unroll
    for (int k = 0; k < KPT; k++) {
        int j = t + k * NT;
        #pragma unroll
        for (int c = NQ - 2; c >= 0; c--) {
            j ^= ((j >> (NQ - 1 - c)) & 1) << (NQ - 2 - c);
        }
        perm[k] = j;
    }
    __syncthreads();

    // ---- circuit ----
    for (int l = 0; l < NL; l++) {
        // 12 fused single-qubit gates
        for (int q = 0; q < NQ; q++) {
            const int pos = NQ - 1 - q;           // bit position (MSB ordering)
            const float2 u00 = U[l][q][0], u01 = U[l][q][1];
            const float2 u10 = U[l][q][2], u11 = U[l][q][3];
            const int lowmask = (1 << pos) - 1;
            #pragma unroll
            for (int k = 0; k < PAIRS / NT; k++) {
                const int p  = t + k * NT;
                const int i0 = ((p >> pos) << (pos + 1)) | (p & lowmask);
                const int i1 = i0 | (1 << pos);
                const float2 s0 = st[i0];
                const float2 s1 = st[i1];
                float2 r0, r1;
                r0.x = u00.x*s0.x - u00.y*s0.y + u01.x*s1.x - u01.y*s1.y;
                r0.y = u00.x*s0.y + u00.y*s0.x + u01.x*s1.y + u01.y*s1.x;
                r1.x = u10.x*s0.x - u10.y*s0.y + u11.x*s1.x - u11.y*s1.y;
                r1.y = u10.x*s0.y + u10.y*s0.x + u11.x*s1.y + u11.y*s1.x;
                st[i0] = r0;
                st[i1] = r1;
            }
            __syncthreads();
        }
        // fused 11-CNOT entangling chain: one permutation pass
        float2 v[KPT];
        #pragma unroll
        for (int k = 0; k < KPT; k++) v[k] = st[perm[k]];
        __syncthreads();
        #pragma unroll
        for (int k = 0; k < KPT; k++) st[t + k * NT] = v[k];
        __syncthreads();
    }

    // ---- <Z_0> : sign = +1 if bit11==0 else -1 ----
    float acc = 0.f;
    #pragma unroll
    for (int k = 0; k < KPT; k++) {
        const int i = t + k * NT;
        const float2 a = st[i];
        const float m = a.x * a.x + a.y * a.y;
        acc += (i & (DIM >> 1)) ? -m : m;
    }
    #pragma unroll
    for (int o = 16; o > 0; o >>= 1) acc += __shfl_xor_sync(0xffffffffu, acc, o);
    if ((t & 31) == 0) red[t >> 5] = acc;
    __syncthreads();
    if (t < 32) {
        float v2 = (t < NT / 32) ? red[t] : 0.f;
        #pragma unroll
        for (int o = 4; o > 0; o >>= 1) v2 += __shfl_xor_sync(0xffffffffu, v2, o);
        if (t == 0) out[b] = v2;
    }
}

extern "C" void kernel_launch(void* const* d_in, const int* in_sizes, int n_in,
                              void* d_out, int out_size)
{
    // metadata order: x (256 floats), params (144 floats). Disambiguate by size.
    const float* x      = (const float*)d_in[0];
    const float* params = (const float*)d_in[1];
    if (n_in >= 2 && in_sizes[0] != 256 && in_sizes[1] == 256) {
        x      = (const float*)d_in[1];
        params = (const float*)d_in[0];
    }
    float* out = (float*)d_out;
    qsim_kernel<<<256, NT>>>(x, params, out);
}

// round 2
// speedup vs baseline: 1.7124x; 1.7124x over previous
#include <cuda_runtime.h>

#define NQ    12
#define DIM   4096
#define NL    4
#define NT    256
#define KPT   16                     // amplitudes per thread (4 local qubits)
#define SW(i) ((i) ^ (((i) >> 4) & 0xF))   // bank-conflict swizzle

struct cplx { float x, y; };

__device__ __forceinline__ cplx cmul(cplx a, cplx b) {
    return { a.x*b.x - a.y*b.y, a.x*b.y + a.y*b.x };
}
__device__ __forceinline__ cplx cadd(cplx a, cplx b) {
    return { a.x + b.x, a.y + b.y };
}
__device__ __forceinline__ void mmul(const cplx* A, const cplx* B, cplx* C) {
    C[0] = cadd(cmul(A[0], B[0]), cmul(A[1], B[2]));
    C[1] = cadd(cmul(A[0], B[1]), cmul(A[1], B[3]));
    C[2] = cadd(cmul(A[2], B[0]), cmul(A[3], B[2]));
    C[3] = cadd(cmul(A[2], B[1]), cmul(A[3], B[3]));
}

// Apply 2x2 gate u on local register bit m of v[16]
__device__ __forceinline__ void apply_level(float2 v[KPT], const float2* __restrict__ u, int m) {
    const float2 u00 = u[0], u01 = u[1], u10 = u[2], u11 = u[3];
    #pragma unroll
    for (int h = 0; h < 8; h++) {
        const int k0 = ((h >> m) << (m + 1)) | (h & ((1 << m) - 1));
        const int k1 = k0 | (1 << m);
        const float2 s0 = v[k0];
        const float2 s1 = v[k1];
        v[k0].x = u00.x*s0.x - u00.y*s0.y + u01.x*s1.x - u01.y*s1.y;
        v[k0].y = u00.x*s0.y + u00.y*s0.x + u01.x*s1.y + u01.y*s1.x;
        v[k1].x = u10.x*s0.x - u10.y*s0.y + u11.x*s1.x - u11.y*s1.y;
        v[k1].y = u10.x*s0.y + u10.y*s0.x + u11.x*s1.y + u11.y*s1.x;
    }
}

__global__ __launch_bounds__(NT)
void qsim_kernel(const float* __restrict__ x,
                 const float* __restrict__ params,
                 float* __restrict__ out)
{
    __shared__ float2 st[DIM];            // 32 KB state (swizzled layout)
    __shared__ float2 U[NL][NQ][4];       // fused per-(layer,qubit) gates
    __shared__ float  red[NT / 32];

    const int t = threadIdx.x;
    const int b = blockIdx.x;

    // ---- build 48 fused gate matrices (one thread each) ----
    if (t < NL * NQ) {
        const int l = t / NQ;
        const int q = t % NQ;
        const float xv = x[b];
        const float x1 = asinf(xv);
        const float x2 = acosf(xv * xv);

        float c, s;
        sincosf(0.5f * x1, &s, &c);
        cplx RY[4]  = { {c,0.f}, {-s,0.f}, {s,0.f}, {c,0.f} };
        sincosf(0.5f * x2, &s, &c);
        cplx RZ[4]  = { {c,-s}, {0.f,0.f}, {0.f,0.f}, {c,s} };

        const float t0 = params[q * (NL * 3) + l * 3 + 0];
        const float t1 = params[q * (NL * 3) + l * 3 + 1];
        const float t2 = params[q * (NL * 3) + l * 3 + 2];

        sincosf(0.5f * t0, &s, &c);
        cplx RX0[4] = { {c,0.f}, {0.f,-s}, {0.f,-s}, {c,0.f} };
        sincosf(0.5f * t1, &s, &c);
        cplx RZ1[4] = { {c,-s}, {0.f,0.f}, {0.f,0.f}, {c,s} };
        sincosf(0.5f * t2, &s, &c);
        cplx RX2[4] = { {c,0.f}, {0.f,-s}, {0.f,-s}, {c,0.f} };

        cplx A[4], B[4];
        mmul(RZ,  RY, A);
        mmul(RX0, A,  B);
        mmul(RZ1, B,  A);
        mmul(RX2, A,  B);
        #pragma unroll
        for (int m = 0; m < 4; m++) U[l][q][m] = make_float2(B[m].x, B[m].y);
    }
    __syncthreads();

    float2 v[KPT];

    for (int l = 0; l < NL; l++) {
        // ======== pass 0: local bits 11..8  (qubits 3..0) ========
        if (l == 0) {
            // start directly from |0...0>: amp 1 at i=0 -> t==0, k==0
            #pragma unroll
            for (int k = 0; k < KPT; k++) v[k] = make_float2(0.f, 0.f);
            if (t == 0) v[0] = make_float2(1.f, 0.f);
        } else {
            // fold previous layer's CNOT chain: new[i] = old[i ^ (i>>1)]
            #pragma unroll
            for (int k = 0; k < KPT; k++) {
                const int i = (k << 8) | t;
                const int j = i ^ (i >> 1);
                v[k] = st[SW(j)];
            }
            __syncthreads();   // gather set != scatter set (perm) -> barrier
        }
        #pragma unroll
        for (int m = 0; m < 4; m++) apply_level(v, &U[l][3 - m][0], m);
        #pragma unroll
        for (int k = 0; k < KPT; k++) st[SW((k << 8) | t)] = v[k];
        __syncthreads();

        // ======== pass 1: local bits 7..4  (qubits 7..4) ========
        {
            const int base = ((t & 0xF0) << 4) | (t & 0x0F);
            #pragma unroll
            for (int k = 0; k < KPT; k++) v[k] = st[SW(base | (k << 4))];
            #pragma unroll
            for (int m = 0; m < 4; m++) apply_level(v, &U[l][7 - m][0], m);
            #pragma unroll
            for (int k = 0; k < KPT; k++) st[SW(base | (k << 4))] = v[k];
            __syncthreads();
        }

        // ======== pass 2: local bits 3..0  (qubits 11..8) ========
        {
            const int base = t << 4;
            #pragma unroll
            for (int k = 0; k < KPT; k++) v[k] = st[SW(base | k)];
            #pragma unroll
            for (int m = 0; m < 4; m++) apply_level(v, &U[l][11 - m][0], m);
            if (l < NL - 1) {
                #pragma unroll
                for (int k = 0; k < KPT; k++) st[SW(base | k)] = v[k];
                __syncthreads();
            }
            // last layer: keep in registers; final CNOT perm preserves bit 11,
            // so the Z-observable sign is just bit 11 of the pre-perm index.
        }
    }

    // ---- <Z_0>: sign = bit 11 of i = (t<<4)|k  ->  bit 7 of t ----
    float acc = 0.f;
    #pragma unroll
    for (int k = 0; k < KPT; k++)
        acc += v[k].x * v[k].x + v[k].y * v[k].y;
    acc = (t & 0x80) ? -acc : acc;

    #pragma unroll
    for (int o = 16; o > 0; o >>= 1) acc += __shfl_xor_sync(0xffffffffu, acc, o);
    if ((t & 31) == 0) red[t >> 5] = acc;
    __syncthreads();
    if (t < 32) {
        float v2 = (t < NT / 32) ? red[t] : 0.f;
        #pragma unroll
        for (int o = 4; o > 0; o >>= 1) v2 += __shfl_xor_sync(0xffffffffu, v2, o);
        if (t == 0) out[b] = v2;
    }
}

extern "C" void kernel_launch(void* const* d_in, const int* in_sizes, int n_in,
                              void* d_out, int out_size)
{
    const float* x      = (const float*)d_in[0];
    const float* params = (const float*)d_in[1];
    if (n_in >= 2 && in_sizes[0] != 256 && in_sizes[1] == 256) {
        x      = (const float*)d_in[1];
        params = (const float*)d_in[0];
    }
    float* out = (float*)d_out;
    qsim_kernel<<<256, NT>>>(x, params, out);
}

// round 3
// speedup vs baseline: 1.8197x; 1.0627x over previous
#include <cuda_runtime.h>

#define NQ    12
#define DIM   4096
#define NL    4
#define NT    256
#define KPT   16                           // amplitudes per thread (4 local qubits)
#define SW(i) ((i) ^ (((i) >> 4) & 0xF))   // bank-conflict swizzle

typedef unsigned long long u64;

struct cplx { float x, y; };

__device__ __forceinline__ cplx cmul(cplx a, cplx b) {
    return { a.x*b.x - a.y*b.y, a.x*b.y + a.y*b.x };
}
__device__ __forceinline__ cplx cadd(cplx a, cplx b) {
    return { a.x + b.x, a.y + b.y };
}
__device__ __forceinline__ void mmul(const cplx* A, const cplx* B, cplx* C) {
    C[0] = cadd(cmul(A[0], B[0]), cmul(A[1], B[2]));
    C[1] = cadd(cmul(A[0], B[1]), cmul(A[1], B[3]));
    C[2] = cadd(cmul(A[2], B[0]), cmul(A[3], B[2]));
    C[3] = cadd(cmul(A[2], B[1]), cmul(A[3], B[3]));
}

// ---- packed f32x2 helpers (Blackwell dual-FP32 pipe) ----
__device__ __forceinline__ u64 mul2(u64 a, u64 b) {
    u64 d; asm("mul.rn.f32x2 %0, %1, %2;" : "=l"(d) : "l"(a), "l"(b)); return d;
}
__device__ __forceinline__ u64 fma2(u64 a, u64 b, u64 c) {
    u64 d; asm("fma.rn.f32x2 %0, %1, %2, %3;" : "=l"(d) : "l"(a), "l"(b), "l"(c)); return d;
}
__device__ __forceinline__ u64 swp(u64 a) {   // (x,y) -> (y,x)
    u64 d;
    asm("{\n\t.reg .b32 lo, hi;\n\tmov.b64 {lo, hi}, %1;\n\tmov.b64 %0, {hi, lo};\n\t}"
        : "=l"(d) : "l"(a));
    return d;
}
__device__ __forceinline__ u64 pk(float lo, float hi) {
    union { float2 f; u64 u; } c; c.f = make_float2(lo, hi); return c.u;
}

// Apply 2x2 complex gate (packed constants up[8]) on local register bit m of v[16].
// up layout: a00,b00,a01,b01,a10,b10,a11,b11 where aXY=(u.x,u.x), bXY=(-u.y,u.y)
__device__ __forceinline__ void apply_level(u64 v[KPT], const u64* __restrict__ up, int m) {
    const u64 a00 = up[0], b00 = up[1], a01 = up[2], b01 = up[3];
    const u64 a10 = up[4], b10 = up[5], a11 = up[6], b11 = up[7];
    #pragma unroll
    for (int h = 0; h < 8; h++) {
        const int k0 = ((h >> m) << (m + 1)) | (h & ((1 << m) - 1));
        const int k1 = k0 | (1 << m);
        const u64 s0  = v[k0];
        const u64 s1  = v[k1];
        const u64 s0s = swp(s0);
        const u64 s1s = swp(s1);
        v[k0] = fma2(b01, s1s, fma2(a01, s1, fma2(b00, s0s, mul2(a00, s0))));
        v[k1] = fma2(b11, s1s, fma2(a11, s1, fma2(b10, s0s, mul2(a10, s0))));
    }
}

__global__ __launch_bounds__(NT)
void qsim_kernel(const float* __restrict__ x,
                 const float* __restrict__ params,
                 float* __restrict__ out)
{
    __shared__ u64  st[DIM];              // 32 KB state, packed (re,im), swizzled
    __shared__ u64  Upk[NL][NQ][8];       // packed fused gate constants (3 KB)
    __shared__ float red[NT / 32];

    const int t = threadIdx.x;
    const int b = blockIdx.x;

    // ---- build 48 fused gate matrices, store packed-f32x2 form ----
    if (t < NL * NQ) {
        const int l = t / NQ;
        const int q = t % NQ;
        const float xv = x[b];
        const float x1 = asinf(xv);
        const float x2 = acosf(xv * xv);

        float c, s;
        sincosf(0.5f * x1, &s, &c);
        cplx RY[4]  = { {c,0.f}, {-s,0.f}, {s,0.f}, {c,0.f} };
        sincosf(0.5f * x2, &s, &c);
        cplx RZ[4]  = { {c,-s}, {0.f,0.f}, {0.f,0.f}, {c,s} };

        const float t0 = params[q * (NL * 3) + l * 3 + 0];
        const float t1 = params[q * (NL * 3) + l * 3 + 1];
        const float t2 = params[q * (NL * 3) + l * 3 + 2];

        sincosf(0.5f * t0, &s, &c);
        cplx RX0[4] = { {c,0.f}, {0.f,-s}, {0.f,-s}, {c,0.f} };
        sincosf(0.5f * t1, &s, &c);
        cplx RZ1[4] = { {c,-s}, {0.f,0.f}, {0.f,0.f}, {c,s} };
        sincosf(0.5f * t2, &s, &c);
        cplx RX2[4] = { {c,0.f}, {0.f,-s}, {0.f,-s}, {c,0.f} };

        cplx A[4], B[4];
        mmul(RZ,  RY, A);
        mmul(RX0, A,  B);
        mmul(RZ1, B,  A);
        mmul(RX2, A,  B);
        #pragma unroll
        for (int m = 0; m < 4; m++) {
            Upk[l][q][2*m]     = pk(B[m].x, B[m].x);    // aXY
            Upk[l][q][2*m + 1] = pk(-B[m].y, B[m].y);   // bXY
        }
    }
    __syncthreads();

    u64 v[KPT];

    for (int l = 0; l < NL; l++) {
        // ======== pass 0: local bits 11..8 (qubits 3..0) ========
        if (l == 0) {
            #pragma unroll
            for (int k = 0; k < KPT; k++) v[k] = 0ull;
            if (t == 0) v[0] = pk(1.f, 0.f);
        } else {
            // fold previous layer's CNOT chain: new[i] = old[i ^ (i>>1)]
            #pragma unroll
            for (int k = 0; k < KPT; k++) {
                const int i = (k << 8) | t;
                const int j = i ^ (i >> 1);
                v[k] = st[SW(j)];
            }
            __syncthreads();
        }
        #pragma unroll
        for (int m = 0; m < 4; m++) apply_level(v, &Upk[l][3 - m][0], m);
        #pragma unroll
        for (int k = 0; k < KPT; k++) st[SW((k << 8) | t)] = v[k];
        __syncthreads();

        // ======== pass 1: local bits 7..4 (qubits 7..4) ========
        {
            const int base = ((t & 0xF0) << 4) | (t & 0x0F);
            #pragma unroll
            for (int k = 0; k < KPT; k++) v[k] = st[SW(base | (k << 4))];
            #pragma unroll
            for (int m = 0; m < 4; m++) apply_level(v, &Upk[l][7 - m][0], m);
            #pragma unroll
            for (int k = 0; k < KPT; k++) st[SW(base | (k << 4))] = v[k];
            __syncthreads();
        }

        // ======== pass 2: local bits 3..0 (qubits 11..8) ========
        {
            const int base = t << 4;
            #pragma unroll
            for (int k = 0; k < KPT; k++) v[k] = st[SW(base | k)];
            #pragma unroll
            for (int m = 0; m < 4; m++) apply_level(v, &Upk[l][11 - m][0], m);
            if (l < NL - 1) {
                #pragma unroll
                for (int k = 0; k < KPT; k++) st[SW(base | k)] = v[k];
                __syncthreads();
            }
            // last layer: stay in registers; CNOT perm preserves bit 11, so the
            // Z sign depends only on bit 11 of the pre-perm index.
        }
    }

    // ---- <Z_0>: sign = bit 11 of i = (t<<4)|k -> bit 7 of t ----
    float acc = 0.f;
    #pragma unroll
    for (int k = 0; k < KPT; k++) {
        union { u64 u; float2 f; } c; c.u = v[k];
        acc += c.f.x * c.f.x + c.f.y * c.f.y;
    }
    acc = (t & 0x80) ? -acc : acc;

    #pragma unroll
    for (int o = 16; o > 0; o >>= 1) acc += __shfl_xor_sync(0xffffffffu, acc, o);
    if ((t & 31) == 0) red[t >> 5] = acc;
    __syncthreads();
    if (t < 32) {
        float v2 = (t < NT / 32) ? red[t] : 0.f;
        #pragma unroll
        for (int o = 4; o > 0; o >>= 1) v2 += __shfl_xor_sync(0xffffffffu, v2, o);
        if (t == 0) out[b] = v2;
    }
}

extern "C" void kernel_launch(void* const* d_in, const int* in_sizes, int n_in,
                              void* d_out, int out_size)
{
    const float* x      = (const float*)d_in[0];
    const float* params = (const float*)d_in[1];
    if (n_in >= 2 && in_sizes[0] != 256 && in_sizes[1] == 256) {
        x      = (const float*)d_in[1];
        params = (const float*)d_in[0];
    }
    float* out = (float*)d_out;
    qsim_kernel<<<256, NT>>>(x, params, out);
}